// round 15
// baseline (speedup 1.0000x reference)
#include <cuda_runtime.h>
#include <cuda_fp16.h>
#include <math.h>
#include <stdint.h>

#define CATOM 512
#define NHEADS 8
#define HDIM 64
#define BATCH 2
#define LSEQ 512
#define NATOMS 4
#define SEQ (LSEQ*NATOMS)      /* 2048 */
#define MROWS (BATCH*SEQ)      /* 4096 */
#define FFDIM 2048
#define QKVN (3*CATOM)
#define MC (MROWS*CATOM)

// ---------------- scratch (device globals: allocation-free) ----------------
__device__ __half g_hh  [MROWS*CATOM];
__device__ __half g_qkv3[3*MROWS*CATOM];   // [q | k | v], each 512-stride
__device__ __half g_aoh [MROWS*CATOM];
__device__ float  g_x1  [MROWS*CATOM];
__device__ __half g_h2h [MROWS*CATOM];
__device__ __half g_f1h [MROWS*FFDIM];
__device__ float  g_bqkv[QKVN];
#define WOFF_Q 0
#define WOFF_O (3*CATOM*CATOM)
#define WOFF_1 (4*CATOM*CATOM)
#define WOFF_2 (4*CATOM*CATOM + FFDIM*CATOM)
#define WTOT   (4*CATOM*CATOM + 2*FFDIM*CATOM)
__device__ __half g_wf[WTOT];

// ======================= helpers =======================
__device__ __forceinline__ uint32_t smem_u32(const void* p) {
    uint32_t a;
    asm("{ .reg .u64 t; cvta.to.shared.u64 t, %1; cvt.u32.u64 %0, t; }" : "=r"(a) : "l"(p));
    return a;
}
__device__ __forceinline__ void cpa16(uint32_t d, const void* g) {
    asm volatile("cp.async.cg.shared.global [%0], [%1], 16;" :: "r"(d), "l"(g));
}
#define CPA_COMMIT() asm volatile("cp.async.commit_group;" ::: "memory")
#define CPA_WAIT1()  asm volatile("cp.async.wait_group 1;" ::: "memory")
#define CPA_WAIT0()  asm volatile("cp.async.wait_group 0;" ::: "memory")

__device__ __forceinline__ void ldm_x4(uint32_t* r, uint32_t addr) {
    asm volatile("ldmatrix.sync.aligned.m8n8.x4.shared.b16 {%0,%1,%2,%3}, [%4];"
        : "=r"(r[0]), "=r"(r[1]), "=r"(r[2]), "=r"(r[3]) : "r"(addr));
}
__device__ __forceinline__ void ldm_x4_t(uint32_t* r, uint32_t addr) {
    asm volatile("ldmatrix.sync.aligned.m8n8.x4.trans.shared.b16 {%0,%1,%2,%3}, [%4];"
        : "=r"(r[0]), "=r"(r[1]), "=r"(r[2]), "=r"(r[3]) : "r"(addr));
}
__device__ __forceinline__ void mma_f16(float* d, const uint32_t* a, uint32_t b0, uint32_t b1) {
    asm volatile("mma.sync.aligned.m16n8k16.row.col.f32.f16.f16.f32 "
        "{%0,%1,%2,%3}, {%4,%5,%6,%7}, {%8,%9}, {%0,%1,%2,%3};"
        : "+f"(d[0]), "+f"(d[1]), "+f"(d[2]), "+f"(d[3])
        : "r"(a[0]), "r"(a[1]), "r"(a[2]), "r"(a[3]), "r"(b0), "r"(b1));
}
#define ONE2 0x3C003C00u   /* half2(1.0, 1.0) */

// ======================= fused weight convert (all 6 -> fp16), MLP=4 =======
#define WSEG (CATOM*CATOM)
#define WFF  (FFDIM*CATOM)
__global__ void __launch_bounds__(256) conv6_kernel(
        const float* __restrict__ w0, const float* __restrict__ w1,
        const float* __restrict__ w2, const float* __restrict__ w3,
        const float* __restrict__ w4, const float* __restrict__ w5,
        __half* __restrict__ dst) {
    // each block covers 4096 float4s (4 per thread, strided for coalescing)
    #pragma unroll
    for (int j = 0; j < 4; j++) {
        long i = (long)blockIdx.x * 1024 + j * 256 + threadIdx.x;
        long e = i * 4;
        const float* src;
        long off;
        if (e < 4L*WSEG) {
            int seg = (int)(e / WSEG);
            src = (seg == 0) ? w0 : (seg == 1) ? w1 : (seg == 2) ? w2 : w3;
            off = e - (long)seg * WSEG;
        } else if (e < 4L*WSEG + WFF) { src = w4; off = e - 4L*WSEG; }
        else                          { src = w5; off = e - 4L*WSEG - WFF; }
        float4 v = *(const float4*)(src + off);
        __half2 p0 = __floats2half2_rn(v.x, v.y);
        __half2 p1 = __floats2half2_rn(v.z, v.w);
        *(__half2*)(dst + e)     = p0;
        *(__half2*)(dst + e + 2) = p1;
    }
}

// ======================= LayerNorm -> fp16 =================================
__global__ void __launch_bounds__(256) ln_half_kernel(const float* __restrict__ x,
                                                      const float* __restrict__ g,
                                                      const float* __restrict__ b,
                                                      __half* __restrict__ hi) {
    int row = blockIdx.x, tid = threadIdx.x;
    const float* xr = x + (size_t)row * CATOM;
    float v0 = xr[tid], v1 = xr[tid + 256];
    float s = v0 + v1, sq = v0*v0 + v1*v1;
    #pragma unroll
    for (int o = 16; o > 0; o >>= 1) {
        s  += __shfl_xor_sync(0xffffffffu, s,  o);
        sq += __shfl_xor_sync(0xffffffffu, sq, o);
    }
    __shared__ float ss[8], sqs[8];
    int w = tid >> 5;
    if ((tid & 31) == 0) { ss[w] = s; sqs[w] = sq; }
    __syncthreads();
    float tot = 0.f, totq = 0.f;
    #pragma unroll
    for (int i = 0; i < 8; i++) { tot += ss[i]; totq += sqs[i]; }
    float mu = tot * (1.0f/CATOM);
    float inv = rsqrtf(totq * (1.0f/CATOM) - mu*mu + 1e-5f);
    size_t o0 = (size_t)row * CATOM;
    float y0 = (v0 - mu) * inv * g[tid] + b[tid];
    float y1 = (v1 - mu) * inv * g[tid+256] + b[tid+256];
    hi[o0 + tid]       = __float2half_rn(y0);
    hi[o0 + tid + 256] = __float2half_rn(y1);
}

// ============== 3-stage pipelined fp16 mma GEMM, 64x128 block tile =========
#define KC 64
#define LDS 72
#define TILE_A_E (64*LDS)
#define TILE_B_E (128*LDS)
#define STAGE_E (TILE_A_E + TILE_B_E)
#define GEMM_SMEM_B (3*STAGE_E*2)      /* 82944 bytes */

__global__ void __launch_bounds__(256, 2)
gemm_mma(const __half* __restrict__ A, const __half* __restrict__ B,
         const float* __restrict__ bias, const float* __restrict__ resid,
         float* __restrict__ Yf, __half* __restrict__ Yh,
         int M, int N, int K, int mode) {
    extern __shared__ __align__(16) __half smg[];

    int tid = threadIdx.x, wid = tid >> 5, lane = tid & 31;
    int n0 = blockIdx.x * 128, m0 = blockIdx.y * 64;
    int wr = wid >> 2, wc = wid & 3;
    int mb = wr * 32, nb = wc * 32;

    float acc[2][4][4];
    #pragma unroll
    for (int mt = 0; mt < 2; mt++)
        #pragma unroll
        for (int nt = 0; nt < 4; nt++)
            #pragma unroll
            for (int i = 0; i < 4; i++) acc[mt][nt][i] = 0.f;

    int lrow = lane & 15, lcol = (lane >> 4) * 8;
    const int nch = K / KC;

    int cr = tid >> 3, cs = (tid & 7) * 8;
    const __half *pa = A + (size_t)(m0 + cr) * K + cs;
    const __half *pb = B + (size_t)(n0 + cr) * K + cs;
    uint32_t sb = smem_u32(smg);
    uint32_t sco = (uint32_t)(cr*LDS + cs) * 2;

    #define G_ISSUE(st, kof) do { \
        uint32_t d_ = sb + (uint32_t)(st)*STAGE_E*2; \
        _Pragma("unroll") \
        for (int i_ = 0; i_ < 2; i_++) \
            cpa16(d_ + sco + i_*(32*LDS*2), pa + (size_t)(i_*32)*K + (kof)); \
        _Pragma("unroll") \
        for (int i_ = 0; i_ < 4; i_++) \
            cpa16(d_ + TILE_A_E*2 + sco + i_*(32*LDS*2), pb + (size_t)(i_*32)*K + (kof)); \
        CPA_COMMIT(); } while (0)

    G_ISSUE(0, 0);
    if (nch > 1) G_ISSUE(1, KC);

    int st = 0;
    for (int c = 0; c < nch; c++) {
        if (c + 1 < nch) { CPA_WAIT1(); } else { CPA_WAIT0(); }
        __syncthreads();
        if (c + 2 < nch) {
            int s2 = st + 2; if (s2 >= 3) s2 -= 3;
            G_ISSUE(s2, (c+2)*KC);
        }

        __half* pA = smg + st*STAGE_E;
        __half* pB = pA + TILE_A_E;

        #pragma unroll
        for (int ks = 0; ks < 4; ks++) {
            uint32_t ah[2][4];
            #pragma unroll
            for (int mt = 0; mt < 2; mt++) {
                int row = mb + mt*16 + lrow, col = ks*16 + lcol;
                ldm_x4(ah[mt], smem_u32(pA + row*LDS + col));
            }
            #pragma unroll
            for (int nbk = 0; nbk < 2; nbk++) {
                uint32_t bh[4];
                int row = nb + nbk*16 + lrow, col = ks*16 + lcol;
                ldm_x4(bh, smem_u32(pB + row*LDS + col));
                #pragma unroll
                for (int wch = 0; wch < 2; wch++) {
                    int nt = nbk*2 + wch;
                    #pragma unroll
                    for (int mt = 0; mt < 2; mt++)
                        mma_f16(acc[mt][nt], ah[mt], bh[wch], bh[wch+2]);
                }
            }
        }
        if (++st >= 3) st = 0;
    }
    #undef G_ISSUE

    int g = lane >> 2, tig = lane & 3;
    #pragma unroll
    for (int mt = 0; mt < 2; mt++) {
        #pragma unroll
        for (int half_ = 0; half_ < 2; half_++) {
            int m = m0 + mb + mt*16 + g + half_*8;
            size_t mrow = (size_t)m * N;
            #pragma unroll
            for (int nt = 0; nt < 4; nt++) {
                int n = n0 + nb + nt*8 + tig*2;
                float v0 = acc[mt][nt][half_*2+0] + bias[n];
                float v1 = acc[mt][nt][half_*2+1] + bias[n+1];
                if (mode == 2) {
                    v0 = 0.5f * v0 * (1.0f + erff(v0 * 0.70710678118654752f));
                    v1 = 0.5f * v1 * (1.0f + erff(v1 * 0.70710678118654752f));
                    *(__half2*)(Yh + mrow + n) = __floats2half2_rn(v0, v1);
                } else if (mode == 3) {
                    int which = n >> 9, col = n & 511;
                    __half* dst = Yh + (size_t)which*MC + (size_t)m*CATOM + col;
                    *(__half2*)dst = __floats2half2_rn(v0, v1);
                } else {
                    if (mode == 1) {
                        float2 rv = *(const float2*)(resid + mrow + n);
                        v0 += rv.x; v1 += rv.y;
                    }
                    *(float2*)(Yf + mrow + n) = make_float2(v0, v1);
                }
            }
        }
    }
}

// ================= Flash attention: fp16 exp, mma-based row sums ===========
#define AP 72
#define AQ_E (128*AP)
#define AKV_E (64*AP)
#define APAIR_E (4*AKV_E)                       /* K0,V0,K1,V1 */
#define ATTN_SMEM_B ((AQ_E + 2*APAIR_E)*2)      /* 92160 bytes */
#define SHIFT_C 3.0f

__device__ __forceinline__ void attn_issue2(__half* dst,
        const __half* kb, const __half* vb, size_t base, int j0, int tid) {
    #pragma unroll
    for (int i = 0; i < 2; i++) {
        int u = tid + i * 256;
        int r = u >> 3, seg = (u & 7) * 8;
        size_t gk0 = base + (size_t)(j0 + r) * CATOM + seg;
        size_t gk1 = base + (size_t)(j0 + 64 + r) * CATOM + seg;
        cpa16(smem_u32(dst +             r*AP + seg), kb + gk0);
        cpa16(smem_u32(dst +   AKV_E  + r*AP + seg), vb + gk0);
        cpa16(smem_u32(dst + 2*AKV_E + r*AP + seg), kb + gk1);
        cpa16(smem_u32(dst + 3*AKV_E + r*AP + seg), vb + gk1);
    }
    CPA_COMMIT();
}

// liacc[4]: mma-accumulated row sums of P (d0,d1: row g; d2,d3: row g+8)
__device__ __forceinline__ void attn_chunk(
        const __half* sK, const __half* sV, int j0,
        const uint32_t aQ[4][4], const float b2c[2],
        float acc[8][4], float liacc[4],
        const int* mrow, int msel,
        int lrow, int lcol, int vkey, int vcol, float scale) {
    float cc_[8][4];
    #pragma unroll
    for (int nt = 0; nt < 8; nt++)
        #pragma unroll
        for (int i = 0; i < 4; i++) cc_[nt][i] = 0.f;
    #pragma unroll
    for (int nbk = 0; nbk < 4; nbk++) {
        uint32_t bk[4][4];
        #pragma unroll
        for (int ks = 0; ks < 4; ks++)
            ldm_x4(bk[ks], smem_u32(sK + (nbk*16 + lrow)*AP + ks*16 + lcol));
        #pragma unroll
        for (int wch = 0; wch < 2; wch++) {
            float* cc = cc_[nbk*2 + wch];
            #pragma unroll
            for (int ks = 0; ks < 4; ks++)
                mma_f16(cc, aQ[ks], bk[ks][wch], bk[ks][wch+2]);
        }
    }

    // p = exp(s*scale + bias - C + mask), computed in fp16; result IS the A frag
    uint32_t aP[4][4];
    #pragma unroll
    for (int nt = 0; nt < 8; nt++) {
        float mk = mrow[(j0 >> 2) + 2*nt + msel] ? 0.f : -1e30f;
        float t0 = fmaf(cc_[nt][0], scale, b2c[0]) + mk;
        float t1 = fmaf(cc_[nt][1], scale, b2c[1]) + mk;
        float t2 = fmaf(cc_[nt][2], scale, b2c[0]) + mk;
        float t3 = fmaf(cc_[nt][3], scale, b2c[1]) + mk;
        __half2 p01 = h2exp(__floats2half2_rn(t0, t1));
        __half2 p23 = h2exp(__floats2half2_rn(t2, t3));
        int ks = nt >> 1, wsel = (nt & 1) * 2;
        aP[ks][wsel]     = *(uint32_t*)&p01;
        aP[ks][wsel + 1] = *(uint32_t*)&p23;
    }

    // row sums via mma with all-ones B (exact quad reduction, fp32 acc)
    #pragma unroll
    for (int ks = 0; ks < 4; ks++)
        mma_f16(liacc, aP[ks], ONE2, ONE2);

    // O += P @ V
    #pragma unroll
    for (int nbk = 0; nbk < 4; nbk++) {
        uint32_t bv[4][4];
        #pragma unroll
        for (int ks = 0; ks < 4; ks++)
            ldm_x4_t(bv[ks], smem_u32(sV + (ks*16 + vkey)*AP + nbk*16 + vcol));
        #pragma unroll
        for (int wch = 0; wch < 2; wch++) {
            float* oo = acc[nbk*2 + wch];
            #pragma unroll
            for (int ks = 0; ks < 4; ks++)
                mma_f16(oo, aP[ks], bv[ks][wch], bv[ks][wch+2]);
        }
    }
}

__global__ void __launch_bounds__(256, 2)
attn_mma(const __half* __restrict__ qkv3, const float* __restrict__ pair_bias,
         const int* __restrict__ mask, __half* __restrict__ outb) {
    extern __shared__ __align__(16) __half sma[];
    __half* sQ = sma;
    const __half* qb = qkv3;
    const __half* kb = qkv3 + MC;
    const __half* vb = qkv3 + 2*MC;

    int q0 = blockIdx.x * 128;
    int bh = blockIdx.y;
    int b = bh >> 3, h = bh & 7;
    int tid = threadIdx.x, wid = tid >> 5, lane = tid & 31;
    int g = lane >> 2, tig = lane & 3;
    int lrow = lane & 15, lcol = (lane >> 4) * 8;
    const float scale = 0.125f;
    size_t base = (size_t)b * SEQ * CATOM + (size_t)h * HDIM;

    #pragma unroll
    for (int i = 0; i < 4; i++) {
        int u = tid + i * 256;
        int r = u >> 3, seg = (u & 7) * 8;
        cpa16(smem_u32(sQ + r*AP + seg), qb + base + (size_t)(q0 + r) * CATOM + seg);
    }
    CPA_COMMIT();
    attn_issue2(sQ + AQ_E, kb, vb, base, 0, tid);
    CPA_WAIT1();
    __syncthreads();

    uint32_t aQ[4][4];
    #pragma unroll
    for (int ks = 0; ks < 4; ks++)
        ldm_x4(aQ[ks], smem_u32(sQ + (wid*16 + lrow)*AP + ks*16 + lcol));

    float b2c[2];
    b2c[0] = pair_bias[h*16 + (g&3)*4 + ((2*tig)&3)]   - SHIFT_C;
    b2c[1] = pair_bias[h*16 + (g&3)*4 + ((2*tig+1)&3)] - SHIFT_C;

    float liacc[4] = {0.f, 0.f, 0.f, 0.f};
    float acc[8][4];
    #pragma unroll
    for (int nt = 0; nt < 8; nt++)
        #pragma unroll
        for (int i = 0; i < 4; i++) acc[nt][i] = 0.f;

    const int* mrow = mask + (size_t)b * LSEQ;
    int msel = tig >> 1;
    int vkey = (lane & 7) | ((lane & 16) >> 1);
    int vcol = lane & 8;

    const int NS = SEQ / 128;   // 16 pair-steps
    for (int s = 0; s < NS; s++) {
        int buf = s & 1;
        if (s + 1 < NS) {
            attn_issue2(sQ + AQ_E + (buf^1)*APAIR_E, kb, vb, base, (s+1)*128, tid);
            CPA_WAIT1();
        } else {
            CPA_WAIT0();
        }
        __syncthreads();
        __half* pp = sQ + AQ_E + buf*APAIR_E;
        int j0 = s * 128;

        attn_chunk(pp,             pp + AKV_E,   j0,      aQ, b2c, acc, liacc, mrow, msel, lrow, lcol, vkey, vcol, scale);
        attn_chunk(pp + 2*AKV_E,   pp + 3*AKV_E, j0 + 64, aQ, b2c, acc, liacc, mrow, msel, lrow, lcol, vkey, vcol, scale);
        __syncthreads();
    }

    float inv0 = 1.0f / liacc[0], inv1 = 1.0f / liacc[2];
    #pragma unroll
    for (int nt = 0; nt < 8; nt++) {
        size_t r0 = base + (size_t)(q0 + wid*16 + g) * CATOM + nt*8 + tig*2;
        size_t r1 = r0 + (size_t)8 * CATOM;
        *(__half2*)(outb + r0) = __floats2half2_rn(acc[nt][0]*inv0, acc[nt][1]*inv0);
        *(__half2*)(outb + r1) = __floats2half2_rn(acc[nt][2]*inv1, acc[nt][3]*inv1);
    }
}

// ---------------- driver ----------------
extern "C" void kernel_launch(void* const* d_in, const int* in_sizes, int n_in,
                              void* d_out, int out_size) {
    const float* atom = (const float*)d_in[0];
    const int* mask = (const int*)d_in[1];
    const float* ln1g = (const float*)d_in[2];
    const float* ln1b = (const float*)d_in[3];
    const float* Wq = (const float*)d_in[4];
    const float* bq = (const float*)d_in[5];
    const float* Wk = (const float*)d_in[6];
    const float* bk = (const float*)d_in[7];
    const float* Wv = (const float*)d_in[8];
    const float* bv = (const float*)d_in[9];
    const float* Wo = (const float*)d_in[10];
    const float* bo = (const float*)d_in[11];
    const float* pb = (const float*)d_in[12];
    const float* ln2g = (const float*)d_in[13];
    const float* ln2b = (const float*)d_in[14];
    const float* W1 = (const float*)d_in[15];
    const float* b1 = (const float*)d_in[16];
    const float* W2 = (const float*)d_in[17];
    const float* b2 = (const float*)d_in[18];
    float* out = (float*)d_out;

    __half *hh_, *qkv3_, *aoh_, *h2h_, *f1h_, *wf_;
    float *x1_, *bqkv_;
    cudaGetSymbolAddress((void**)&hh_,   g_hh);
    cudaGetSymbolAddress((void**)&qkv3_, g_qkv3);
    cudaGetSymbolAddress((void**)&aoh_,  g_aoh);
    cudaGetSymbolAddress((void**)&x1_,   g_x1);
    cudaGetSymbolAddress((void**)&h2h_,  g_h2h);
    cudaGetSymbolAddress((void**)&f1h_,  g_f1h);
    cudaGetSymbolAddress((void**)&wf_,   g_wf);
    cudaGetSymbolAddress((void**)&bqkv_, g_bqkv);

    cudaFuncSetAttribute(gemm_mma, cudaFuncAttributeMaxDynamicSharedMemorySize, GEMM_SMEM_B);
    cudaFuncSetAttribute(attn_mma, cudaFuncAttributeMaxDynamicSharedMemorySize, ATTN_SMEM_B);

    // pack qkv biases
    cudaMemcpyAsync(bqkv_,           bq, CATOM*sizeof(float), cudaMemcpyDeviceToDevice);
    cudaMemcpyAsync(bqkv_ + CATOM,   bk, CATOM*sizeof(float), cudaMemcpyDeviceToDevice);
    cudaMemcpyAsync(bqkv_ + 2*CATOM, bv, CATOM*sizeof(float), cudaMemcpyDeviceToDevice);

    // fused weight convert -> fp16 (MLP=4)
    conv6_kernel<<<WTOT/4/1024, 256>>>(Wq, Wk, Wv, Wo, W1, W2, wf_);

    // 1) h = LN1(x) -> fp16
    ln_half_kernel<<<MROWS, 256>>>(atom, ln1g, ln1b, hh_);
    // 2) fused qkv GEMM, split epilogue into q|k|v contiguous buffers
    gemm_mma<<<dim3(QKVN/128, MROWS/64), 256, GEMM_SMEM_B>>>(hh_, wf_+WOFF_Q, bqkv_, nullptr, nullptr, qkv3_, MROWS, QKVN, CATOM, 3);
    // 3) attention
    attn_mma<<<dim3(SEQ/128, BATCH*NHEADS), 256, ATTN_SMEM_B>>>(qkv3_, pb, mask, aoh_);
    // 4) x1 = x + ao @ Wo^T + bo  (fp32)
    gemm_mma<<<dim3(CATOM/128, MROWS/64), 256, GEMM_SMEM_B>>>(aoh_, wf_+WOFF_O, bo, atom, x1_, nullptr, MROWS, CATOM, CATOM, 1);
    // 5) h2 = LN2(x1) -> fp16
    ln_half_kernel<<<MROWS, 256>>>(x1_, ln2g, ln2b, h2h_);
    // 6) f1 = gelu(h2 @ W1^T + b1) -> fp16
    gemm_mma<<<dim3(FFDIM/128, MROWS/64), 256, GEMM_SMEM_B>>>(h2h_, wf_+WOFF_1, b1, nullptr, nullptr, f1h_, MROWS, FFDIM, CATOM, 2);
    // 7) out = x1 + f1 @ W2^T + b2  (fp32 to d_out)
    gemm_mma<<<dim3(CATOM/128, MROWS/64), 256, GEMM_SMEM_B>>>(f1h_, wf_+WOFF_2, b2, x1_, out, nullptr, MROWS, CATOM, FFDIM, 1);
}

// round 16
// speedup vs baseline: 1.0165x; 1.0165x over previous
#include <cuda_runtime.h>
#include <cuda_fp16.h>
#include <math.h>
#include <stdint.h>

#define CATOM 512
#define NHEADS 8
#define HDIM 64
#define BATCH 2
#define LSEQ 512
#define NATOMS 4
#define SEQ (LSEQ*NATOMS)      /* 2048 */
#define MROWS (BATCH*SEQ)      /* 4096 */
#define FFDIM 2048
#define QKVN (3*CATOM)
#define MC (MROWS*CATOM)

// ---------------- scratch (device globals: allocation-free) ----------------
__device__ __half g_hh  [MROWS*CATOM];
__device__ __half g_qkv3[3*MROWS*CATOM];   // [q | k | v], each 512-stride
__device__ __half g_aoh [MROWS*CATOM];
__device__ float  g_x1  [MROWS*CATOM];
__device__ __half g_h2h [MROWS*CATOM];
__device__ __half g_f1h [MROWS*FFDIM];
__device__ float  g_bqkv[QKVN];
#define WOFF_Q 0
#define WOFF_O (3*CATOM*CATOM)
#define WOFF_1 (4*CATOM*CATOM)
#define WOFF_2 (4*CATOM*CATOM + FFDIM*CATOM)
#define WTOT   (4*CATOM*CATOM + 2*FFDIM*CATOM)
__device__ __half g_wf[WTOT];

// ======================= helpers =======================
__device__ __forceinline__ uint32_t smem_u32(const void* p) {
    uint32_t a;
    asm("{ .reg .u64 t; cvta.to.shared.u64 t, %1; cvt.u32.u64 %0, t; }" : "=r"(a) : "l"(p));
    return a;
}
__device__ __forceinline__ void cpa16(uint32_t d, const void* g) {
    asm volatile("cp.async.cg.shared.global [%0], [%1], 16;" :: "r"(d), "l"(g));
}
#define CPA_COMMIT() asm volatile("cp.async.commit_group;" ::: "memory")
#define CPA_WAIT1()  asm volatile("cp.async.wait_group 1;" ::: "memory")
#define CPA_WAIT0()  asm volatile("cp.async.wait_group 0;" ::: "memory")

__device__ __forceinline__ void ldm_x4(uint32_t* r, uint32_t addr) {
    asm volatile("ldmatrix.sync.aligned.m8n8.x4.shared.b16 {%0,%1,%2,%3}, [%4];"
        : "=r"(r[0]), "=r"(r[1]), "=r"(r[2]), "=r"(r[3]) : "r"(addr));
}
__device__ __forceinline__ void ldm_x4_t(uint32_t* r, uint32_t addr) {
    asm volatile("ldmatrix.sync.aligned.m8n8.x4.trans.shared.b16 {%0,%1,%2,%3}, [%4];"
        : "=r"(r[0]), "=r"(r[1]), "=r"(r[2]), "=r"(r[3]) : "r"(addr));
}
__device__ __forceinline__ void mma_f16(float* d, const uint32_t* a, uint32_t b0, uint32_t b1) {
    asm volatile("mma.sync.aligned.m16n8k16.row.col.f32.f16.f16.f32 "
        "{%0,%1,%2,%3}, {%4,%5,%6,%7}, {%8,%9}, {%0,%1,%2,%3};"
        : "+f"(d[0]), "+f"(d[1]), "+f"(d[2]), "+f"(d[3])
        : "r"(a[0]), "r"(a[1]), "r"(a[2]), "r"(a[3]), "r"(b0), "r"(b1));
}
__device__ __forceinline__ uint32_t pack_f16(float lo, float hi) {
    uint32_t d;
    asm("cvt.rn.f16x2.f32 %0, %1, %2;" : "=r"(d) : "f"(hi), "f"(lo));
    return d;
}

// ======================= fused weight convert (all 6 -> fp16), MLP=4 =======
#define WSEG (CATOM*CATOM)
#define WFF  (FFDIM*CATOM)
__global__ void __launch_bounds__(256) conv6_kernel(
        const float* __restrict__ w0, const float* __restrict__ w1,
        const float* __restrict__ w2, const float* __restrict__ w3,
        const float* __restrict__ w4, const float* __restrict__ w5,
        __half* __restrict__ dst) {
    #pragma unroll
    for (int j = 0; j < 4; j++) {
        long i = (long)blockIdx.x * 1024 + j * 256 + threadIdx.x;
        long e = i * 4;
        const float* src;
        long off;
        if (e < 4L*WSEG) {
            int seg = (int)(e / WSEG);
            src = (seg == 0) ? w0 : (seg == 1) ? w1 : (seg == 2) ? w2 : w3;
            off = e - (long)seg * WSEG;
        } else if (e < 4L*WSEG + WFF) { src = w4; off = e - 4L*WSEG; }
        else                          { src = w5; off = e - 4L*WSEG - WFF; }
        float4 v = *(const float4*)(src + off);
        __half2 p0 = __floats2half2_rn(v.x, v.y);
        __half2 p1 = __floats2half2_rn(v.z, v.w);
        *(__half2*)(dst + e)     = p0;
        *(__half2*)(dst + e + 2) = p1;
    }
}

// ======================= LayerNorm -> fp16 =================================
__global__ void __launch_bounds__(256) ln_half_kernel(const float* __restrict__ x,
                                                      const float* __restrict__ g,
                                                      const float* __restrict__ b,
                                                      __half* __restrict__ hi) {
    int row = blockIdx.x, tid = threadIdx.x;
    const float* xr = x + (size_t)row * CATOM;
    float v0 = xr[tid], v1 = xr[tid + 256];
    float s = v0 + v1, sq = v0*v0 + v1*v1;
    #pragma unroll
    for (int o = 16; o > 0; o >>= 1) {
        s  += __shfl_xor_sync(0xffffffffu, s,  o);
        sq += __shfl_xor_sync(0xffffffffu, sq, o);
    }
    __shared__ float ss[8], sqs[8];
    int w = tid >> 5;
    if ((tid & 31) == 0) { ss[w] = s; sqs[w] = sq; }
    __syncthreads();
    float tot = 0.f, totq = 0.f;
    #pragma unroll
    for (int i = 0; i < 8; i++) { tot += ss[i]; totq += sqs[i]; }
    float mu = tot * (1.0f/CATOM);
    float inv = rsqrtf(totq * (1.0f/CATOM) - mu*mu + 1e-5f);
    size_t o0 = (size_t)row * CATOM;
    float y0 = (v0 - mu) * inv * g[tid] + b[tid];
    float y1 = (v1 - mu) * inv * g[tid+256] + b[tid+256];
    hi[o0 + tid]       = __float2half_rn(y0);
    hi[o0 + tid + 256] = __float2half_rn(y1);
}

// ============== 3-stage pipelined fp16 mma GEMM, 64x128 block tile =========
#define KC 64
#define LDS 72
#define TILE_A_E (64*LDS)
#define TILE_B_E (128*LDS)
#define STAGE_E (TILE_A_E + TILE_B_E)
#define GEMM_SMEM_B (3*STAGE_E*2)      /* 82944 bytes */

__global__ void __launch_bounds__(256, 2)
gemm_mma(const __half* __restrict__ A, const __half* __restrict__ B,
         const float* __restrict__ bias, const float* __restrict__ resid,
         float* __restrict__ Yf, __half* __restrict__ Yh,
         int M, int N, int K, int mode) {
    extern __shared__ __align__(16) __half smg[];

    int tid = threadIdx.x, wid = tid >> 5, lane = tid & 31;
    int n0 = blockIdx.x * 128, m0 = blockIdx.y * 64;
    int wr = wid >> 2, wc = wid & 3;
    int mb = wr * 32, nb = wc * 32;

    float acc[2][4][4];
    #pragma unroll
    for (int mt = 0; mt < 2; mt++)
        #pragma unroll
        for (int nt = 0; nt < 4; nt++)
            #pragma unroll
            for (int i = 0; i < 4; i++) acc[mt][nt][i] = 0.f;

    int lrow = lane & 15, lcol = (lane >> 4) * 8;
    const int nch = K / KC;

    int cr = tid >> 3, cs = (tid & 7) * 8;
    const __half *pa = A + (size_t)(m0 + cr) * K + cs;
    const __half *pb = B + (size_t)(n0 + cr) * K + cs;
    uint32_t sb = smem_u32(smg);
    uint32_t sco = (uint32_t)(cr*LDS + cs) * 2;

    #define G_ISSUE(st, kof) do { \
        uint32_t d_ = sb + (uint32_t)(st)*STAGE_E*2; \
        _Pragma("unroll") \
        for (int i_ = 0; i_ < 2; i_++) \
            cpa16(d_ + sco + i_*(32*LDS*2), pa + (size_t)(i_*32)*K + (kof)); \
        _Pragma("unroll") \
        for (int i_ = 0; i_ < 4; i_++) \
            cpa16(d_ + TILE_A_E*2 + sco + i_*(32*LDS*2), pb + (size_t)(i_*32)*K + (kof)); \
        CPA_COMMIT(); } while (0)

    G_ISSUE(0, 0);
    if (nch > 1) G_ISSUE(1, KC);

    int st = 0;
    for (int c = 0; c < nch; c++) {
        if (c + 1 < nch) { CPA_WAIT1(); } else { CPA_WAIT0(); }
        __syncthreads();
        if (c + 2 < nch) {
            int s2 = st + 2; if (s2 >= 3) s2 -= 3;
            G_ISSUE(s2, (c+2)*KC);
        }

        __half* pA = smg + st*STAGE_E;
        __half* pB = pA + TILE_A_E;

        #pragma unroll
        for (int ks = 0; ks < 4; ks++) {
            uint32_t ah[2][4];
            #pragma unroll
            for (int mt = 0; mt < 2; mt++) {
                int row = mb + mt*16 + lrow, col = ks*16 + lcol;
                ldm_x4(ah[mt], smem_u32(pA + row*LDS + col));
            }
            #pragma unroll
            for (int nbk = 0; nbk < 2; nbk++) {
                uint32_t bh[4];
                int row = nb + nbk*16 + lrow, col = ks*16 + lcol;
                ldm_x4(bh, smem_u32(pB + row*LDS + col));
                #pragma unroll
                for (int wch = 0; wch < 2; wch++) {
                    int nt = nbk*2 + wch;
                    #pragma unroll
                    for (int mt = 0; mt < 2; mt++)
                        mma_f16(acc[mt][nt], ah[mt], bh[wch], bh[wch+2]);
                }
            }
        }
        if (++st >= 3) st = 0;
    }
    #undef G_ISSUE

    int g = lane >> 2, tig = lane & 3;
    #pragma unroll
    for (int mt = 0; mt < 2; mt++) {
        #pragma unroll
        for (int half_ = 0; half_ < 2; half_++) {
            int m = m0 + mb + mt*16 + g + half_*8;
            size_t mrow = (size_t)m * N;
            #pragma unroll
            for (int nt = 0; nt < 4; nt++) {
                int n = n0 + nb + nt*8 + tig*2;
                float v0 = acc[mt][nt][half_*2+0] + bias[n];
                float v1 = acc[mt][nt][half_*2+1] + bias[n+1];
                if (mode == 2) {
                    v0 = 0.5f * v0 * (1.0f + erff(v0 * 0.70710678118654752f));
                    v1 = 0.5f * v1 * (1.0f + erff(v1 * 0.70710678118654752f));
                    *(__half2*)(Yh + mrow + n) = __floats2half2_rn(v0, v1);
                } else if (mode == 3) {
                    int which = n >> 9, col = n & 511;
                    __half* dst = Yh + (size_t)which*MC + (size_t)m*CATOM + col;
                    *(__half2*)dst = __floats2half2_rn(v0, v1);
                } else {
                    if (mode == 1) {
                        float2 rv = *(const float2*)(resid + mrow + n);
                        v0 += rv.x; v1 += rv.y;
                    }
                    *(float2*)(Yf + mrow + n) = make_float2(v0, v1);
                }
            }
        }
    }
}

// ================= Flash attention: fixed-shift softmax, paired chunks =====
// (round-14 proven version: __expf + scalar li + deferred shuffle reduction)
#define AP 72
#define AQ_E (128*AP)
#define AKV_E (64*AP)
#define APAIR_E (4*AKV_E)                       /* K0,V0,K1,V1 */
#define ATTN_SMEM_B ((AQ_E + 2*APAIR_E)*2)      /* 92160 bytes */
#define SHIFT_C 3.0f

__device__ __forceinline__ void attn_issue2(__half* dst,
        const __half* kb, const __half* vb, size_t base, int j0, int tid) {
    #pragma unroll
    for (int i = 0; i < 2; i++) {
        int u = tid + i * 256;
        int r = u >> 3, seg = (u & 7) * 8;
        size_t gk0 = base + (size_t)(j0 + r) * CATOM + seg;
        size_t gk1 = base + (size_t)(j0 + 64 + r) * CATOM + seg;
        cpa16(smem_u32(dst +             r*AP + seg), kb + gk0);
        cpa16(smem_u32(dst +   AKV_E  + r*AP + seg), vb + gk0);
        cpa16(smem_u32(dst + 2*AKV_E + r*AP + seg), kb + gk1);
        cpa16(smem_u32(dst + 3*AKV_E + r*AP + seg), vb + gk1);
    }
    CPA_COMMIT();
}

__device__ __forceinline__ void attn_chunk(
        const __half* sK, const __half* sV, int j0,
        const uint32_t aQ[4][4], const float b2c[2],
        float acc[8][4], float li[2],
        const int* mrow, int msel,
        int lrow, int lcol, int vkey, int vcol, float scale) {
    float cc_[8][4];
    #pragma unroll
    for (int nt = 0; nt < 8; nt++)
        #pragma unroll
        for (int i = 0; i < 4; i++) cc_[nt][i] = 0.f;
    #pragma unroll
    for (int nbk = 0; nbk < 4; nbk++) {
        uint32_t bk[4][4];
        #pragma unroll
        for (int ks = 0; ks < 4; ks++)
            ldm_x4(bk[ks], smem_u32(sK + (nbk*16 + lrow)*AP + ks*16 + lcol));
        #pragma unroll
        for (int wch = 0; wch < 2; wch++) {
            float* cc = cc_[nbk*2 + wch];
            #pragma unroll
            for (int ks = 0; ks < 4; ks++)
                mma_f16(cc, aQ[ks], bk[ks][wch], bk[ks][wch+2]);
        }
    }

    #pragma unroll
    for (int nt = 0; nt < 8; nt++) {
        float mk = mrow[(j0 >> 2) + 2*nt + msel] ? 0.f : -1e30f;
        cc_[nt][0] = __expf(fmaf(cc_[nt][0], scale, b2c[0]) + mk);
        cc_[nt][1] = __expf(fmaf(cc_[nt][1], scale, b2c[1]) + mk);
        cc_[nt][2] = __expf(fmaf(cc_[nt][2], scale, b2c[0]) + mk);
        cc_[nt][3] = __expf(fmaf(cc_[nt][3], scale, b2c[1]) + mk);
        li[0] += cc_[nt][0] + cc_[nt][1];
        li[1] += cc_[nt][2] + cc_[nt][3];
    }

    uint32_t aP[4][4];
    #pragma unroll
    for (int ks = 0; ks < 4; ks++) {
        aP[ks][0] = pack_f16(cc_[2*ks][0],   cc_[2*ks][1]);
        aP[ks][1] = pack_f16(cc_[2*ks][2],   cc_[2*ks][3]);
        aP[ks][2] = pack_f16(cc_[2*ks+1][0], cc_[2*ks+1][1]);
        aP[ks][3] = pack_f16(cc_[2*ks+1][2], cc_[2*ks+1][3]);
    }

    #pragma unroll
    for (int nbk = 0; nbk < 4; nbk++) {
        uint32_t bv[4][4];
        #pragma unroll
        for (int ks = 0; ks < 4; ks++)
            ldm_x4_t(bv[ks], smem_u32(sV + (ks*16 + vkey)*AP + nbk*16 + vcol));
        #pragma unroll
        for (int wch = 0; wch < 2; wch++) {
            float* oo = acc[nbk*2 + wch];
            #pragma unroll
            for (int ks = 0; ks < 4; ks++)
                mma_f16(oo, aP[ks], bv[ks][wch], bv[ks][wch+2]);
        }
    }
}

__global__ void __launch_bounds__(256, 2)
attn_mma(const __half* __restrict__ qkv3, const float* __restrict__ pair_bias,
         const int* __restrict__ mask, __half* __restrict__ outb) {
    extern __shared__ __align__(16) __half sma[];
    __half* sQ = sma;
    const __half* qb = qkv3;
    const __half* kb = qkv3 + MC;
    const __half* vb = qkv3 + 2*MC;

    int q0 = blockIdx.x * 128;
    int bh = blockIdx.y;
    int b = bh >> 3, h = bh & 7;
    int tid = threadIdx.x, wid = tid >> 5, lane = tid & 31;
    int g = lane >> 2, tig = lane & 3;
    int lrow = lane & 15, lcol = (lane >> 4) * 8;
    const float scale = 0.125f;
    size_t base = (size_t)b * SEQ * CATOM + (size_t)h * HDIM;

    #pragma unroll
    for (int i = 0; i < 4; i++) {
        int u = tid + i * 256;
        int r = u >> 3, seg = (u & 7) * 8;
        cpa16(smem_u32(sQ + r*AP + seg), qb + base + (size_t)(q0 + r) * CATOM + seg);
    }
    CPA_COMMIT();
    attn_issue2(sQ + AQ_E, kb, vb, base, 0, tid);
    CPA_WAIT1();
    __syncthreads();

    uint32_t aQ[4][4];
    #pragma unroll
    for (int ks = 0; ks < 4; ks++)
        ldm_x4(aQ[ks], smem_u32(sQ + (wid*16 + lrow)*AP + ks*16 + lcol));

    float b2c[2];
    b2c[0] = pair_bias[h*16 + (g&3)*4 + ((2*tig)&3)]   - SHIFT_C;
    b2c[1] = pair_bias[h*16 + (g&3)*4 + ((2*tig+1)&3)] - SHIFT_C;

    float li[2] = {0.f, 0.f};
    float acc[8][4];
    #pragma unroll
    for (int nt = 0; nt < 8; nt++)
        #pragma unroll
        for (int i = 0; i < 4; i++) acc[nt][i] = 0.f;

    const int* mrow = mask + (size_t)b * LSEQ;
    int msel = tig >> 1;
    int vkey = (lane & 7) | ((lane & 16) >> 1);
    int vcol = lane & 8;

    const int NS = SEQ / 128;   // 16 pair-steps
    for (int s = 0; s < NS; s++) {
        int buf = s & 1;
        if (s + 1 < NS) {
            attn_issue2(sQ + AQ_E + (buf^1)*APAIR_E, kb, vb, base, (s+1)*128, tid);
            CPA_WAIT1();
        } else {
            CPA_WAIT0();
        }
        __syncthreads();
        __half* pp = sQ + AQ_E + buf*APAIR_E;
        int j0 = s * 128;

        attn_chunk(pp,             pp + AKV_E,   j0,      aQ, b2c, acc, li, mrow, msel, lrow, lcol, vkey, vcol, scale);
        attn_chunk(pp + 2*AKV_E,   pp + 3*AKV_E, j0 + 64, aQ, b2c, acc, li, mrow, msel, lrow, lcol, vkey, vcol, scale);
        __syncthreads();
    }

    #pragma unroll
    for (int o = 1; o <= 2; o <<= 1) {
        li[0] += __shfl_xor_sync(0xffffffffu, li[0], o);
        li[1] += __shfl_xor_sync(0xffffffffu, li[1], o);
    }

    float inv0 = 1.0f / li[0], inv1 = 1.0f / li[1];
    #pragma unroll
    for (int nt = 0; nt < 8; nt++) {
        size_t r0 = base + (size_t)(q0 + wid*16 + g) * CATOM + nt*8 + tig*2;
        size_t r1 = r0 + (size_t)8 * CATOM;
        *(__half2*)(outb + r0) = __floats2half2_rn(acc[nt][0]*inv0, acc[nt][1]*inv0);
        *(__half2*)(outb + r1) = __floats2half2_rn(acc[nt][2]*inv1, acc[nt][3]*inv1);
    }
}

// ---------------- driver ----------------
extern "C" void kernel_launch(void* const* d_in, const int* in_sizes, int n_in,
                              void* d_out, int out_size) {
    const float* atom = (const float*)d_in[0];
    const int* mask = (const int*)d_in[1];
    const float* ln1g = (const float*)d_in[2];
    const float* ln1b = (const float*)d_in[3];
    const float* Wq = (const float*)d_in[4];
    const float* bq = (const float*)d_in[5];
    const float* Wk = (const float*)d_in[6];
    const float* bk = (const float*)d_in[7];
    const float* Wv = (const float*)d_in[8];
    const float* bv = (const float*)d_in[9];
    const float* Wo = (const float*)d_in[10];
    const float* bo = (const float*)d_in[11];
    const float* pb = (const float*)d_in[12];
    const float* ln2g = (const float*)d_in[13];
    const float* ln2b = (const float*)d_in[14];
    const float* W1 = (const float*)d_in[15];
    const float* b1 = (const float*)d_in[16];
    const float* W2 = (const float*)d_in[17];
    const float* b2 = (const float*)d_in[18];
    float* out = (float*)d_out;

    __half *hh_, *qkv3_, *aoh_, *h2h_, *f1h_, *wf_;
    float *x1_, *bqkv_;
    cudaGetSymbolAddress((void**)&hh_,   g_hh);
    cudaGetSymbolAddress((void**)&qkv3_, g_qkv3);
    cudaGetSymbolAddress((void**)&aoh_,  g_aoh);
    cudaGetSymbolAddress((void**)&x1_,   g_x1);
    cudaGetSymbolAddress((void**)&h2h_,  g_h2h);
    cudaGetSymbolAddress((void**)&f1h_,  g_f1h);
    cudaGetSymbolAddress((void**)&wf_,   g_wf);
    cudaGetSymbolAddress((void**)&bqkv_, g_bqkv);

    cudaFuncSetAttribute(gemm_mma, cudaFuncAttributeMaxDynamicSharedMemorySize, GEMM_SMEM_B);
    cudaFuncSetAttribute(attn_mma, cudaFuncAttributeMaxDynamicSharedMemorySize, ATTN_SMEM_B);

    // pack qkv biases
    cudaMemcpyAsync(bqkv_,           bq, CATOM*sizeof(float), cudaMemcpyDeviceToDevice);
    cudaMemcpyAsync(bqkv_ + CATOM,   bk, CATOM*sizeof(float), cudaMemcpyDeviceToDevice);
    cudaMemcpyAsync(bqkv_ + 2*CATOM, bv, CATOM*sizeof(float), cudaMemcpyDeviceToDevice);

    // fused weight convert -> fp16 (MLP=4)
    conv6_kernel<<<WTOT/4/1024, 256>>>(Wq, Wk, Wv, Wo, W1, W2, wf_);

    // 1) h = LN1(x) -> fp16
    ln_half_kernel<<<MROWS, 256>>>(atom, ln1g, ln1b, hh_);
    // 2) fused qkv GEMM, split epilogue into q|k|v contiguous buffers
    gemm_mma<<<dim3(QKVN/128, MROWS/64), 256, GEMM_SMEM_B>>>(hh_, wf_+WOFF_Q, bqkv_, nullptr, nullptr, qkv3_, MROWS, QKVN, CATOM, 3);
    // 3) attention
    attn_mma<<<dim3(SEQ/128, BATCH*NHEADS), 256, ATTN_SMEM_B>>>(qkv3_, pb, mask, aoh_);
    // 4) x1 = x + ao @ Wo^T + bo  (fp32)
    gemm_mma<<<dim3(CATOM/128, MROWS/64), 256, GEMM_SMEM_B>>>(aoh_, wf_+WOFF_O, bo, atom, x1_, nullptr, MROWS, CATOM, CATOM, 1);
    // 5) h2 = LN2(x1) -> fp16
    ln_half_kernel<<<MROWS, 256>>>(x1_, ln2g, ln2b, h2h_);
    // 6) f1 = gelu(h2 @ W1^T + b1) -> fp16
    gemm_mma<<<dim3(FFDIM/128, MROWS/64), 256, GEMM_SMEM_B>>>(h2h_, wf_+WOFF_1, b1, nullptr, nullptr, f1h_, MROWS, FFDIM, CATOM, 2);
    // 7) out = x1 + f1 @ W2^T + b2  (fp32 to d_out)
    gemm_mma<<<dim3(CATOM/128, MROWS/64), 256, GEMM_SMEM_B>>>(f1h_, wf_+WOFF_2, b2, x1_, out, nullptr, MROWS, CATOM, FFDIM, 1);
}

// round 17
// speedup vs baseline: 1.0327x; 1.0159x over previous
#include <cuda_runtime.h>
#include <cuda_fp16.h>
#include <math.h>
#include <stdint.h>

#define CATOM 512
#define NHEADS 8
#define HDIM 64
#define BATCH 2
#define LSEQ 512
#define NATOMS 4
#define SEQ (LSEQ*NATOMS)      /* 2048 */
#define MROWS (BATCH*SEQ)      /* 4096 */
#define FFDIM 2048
#define QKVN (3*CATOM)
#define MC (MROWS*CATOM)

// ---------------- scratch (device globals: allocation-free) ----------------
__device__ __half g_hh  [MROWS*CATOM];
__device__ __half g_qkv3[3*MROWS*CATOM];   // [q | k | v], each 512-stride
__device__ __half g_aoh [MROWS*CATOM];
__device__ float  g_x1  [MROWS*CATOM];
__device__ __half g_h2h [MROWS*CATOM];
__device__ __half g_f1h [MROWS*FFDIM];
#define WOFF_Q 0
#define WOFF_O (3*CATOM*CATOM)
#define WOFF_1 (4*CATOM*CATOM)
#define WOFF_2 (4*CATOM*CATOM + FFDIM*CATOM)
#define WTOT   (4*CATOM*CATOM + 2*FFDIM*CATOM)
__device__ __half g_wf[WTOT];

// ======================= helpers =======================
__device__ __forceinline__ uint32_t smem_u32(const void* p) {
    uint32_t a;
    asm("{ .reg .u64 t; cvta.to.shared.u64 t, %1; cvt.u32.u64 %0, t; }" : "=r"(a) : "l"(p));
    return a;
}
__device__ __forceinline__ void cpa16(uint32_t d, const void* g) {
    asm volatile("cp.async.cg.shared.global [%0], [%1], 16;" :: "r"(d), "l"(g));
}
#define CPA_COMMIT() asm volatile("cp.async.commit_group;" ::: "memory")
#define CPA_WAIT1()  asm volatile("cp.async.wait_group 1;" ::: "memory")
#define CPA_WAIT0()  asm volatile("cp.async.wait_group 0;" ::: "memory")

__device__ __forceinline__ void ldm_x4(uint32_t* r, uint32_t addr) {
    asm volatile("ldmatrix.sync.aligned.m8n8.x4.shared.b16 {%0,%1,%2,%3}, [%4];"
        : "=r"(r[0]), "=r"(r[1]), "=r"(r[2]), "=r"(r[3]) : "r"(addr));
}
__device__ __forceinline__ void ldm_x4_t(uint32_t* r, uint32_t addr) {
    asm volatile("ldmatrix.sync.aligned.m8n8.x4.trans.shared.b16 {%0,%1,%2,%3}, [%4];"
        : "=r"(r[0]), "=r"(r[1]), "=r"(r[2]), "=r"(r[3]) : "r"(addr));
}
__device__ __forceinline__ void mma_f16(float* d, const uint32_t* a, uint32_t b0, uint32_t b1) {
    asm volatile("mma.sync.aligned.m16n8k16.row.col.f32.f16.f16.f32 "
        "{%0,%1,%2,%3}, {%4,%5,%6,%7}, {%8,%9}, {%0,%1,%2,%3};"
        : "+f"(d[0]), "+f"(d[1]), "+f"(d[2]), "+f"(d[3])
        : "r"(a[0]), "r"(a[1]), "r"(a[2]), "r"(a[3]), "r"(b0), "r"(b1));
}
__device__ __forceinline__ uint32_t pack_f16(float lo, float hi) {
    uint32_t d;
    asm("cvt.rn.f16x2.f32 %0, %1, %2;" : "=r"(d) : "f"(hi), "f"(lo));
    return d;
}

// ======================= fused weight convert (all 6 -> fp16), MLP=4 =======
#define WSEG (CATOM*CATOM)
#define WFF  (FFDIM*CATOM)
__global__ void __launch_bounds__(256) conv6_kernel(
        const float* __restrict__ w0, const float* __restrict__ w1,
        const float* __restrict__ w2, const float* __restrict__ w3,
        const float* __restrict__ w4, const float* __restrict__ w5,
        __half* __restrict__ dst) {
    #pragma unroll
    for (int j = 0; j < 4; j++) {
        long i = (long)blockIdx.x * 1024 + j * 256 + threadIdx.x;
        long e = i * 4;
        const float* src;
        long off;
        if (e < 4L*WSEG) {
            int seg = (int)(e / WSEG);
            src = (seg == 0) ? w0 : (seg == 1) ? w1 : (seg == 2) ? w2 : w3;
            off = e - (long)seg * WSEG;
        } else if (e < 4L*WSEG + WFF) { src = w4; off = e - 4L*WSEG; }
        else                          { src = w5; off = e - 4L*WSEG - WFF; }
        float4 v = *(const float4*)(src + off);
        __half2 p0 = __floats2half2_rn(v.x, v.y);
        __half2 p1 = __floats2half2_rn(v.z, v.w);
        *(__half2*)(dst + e)     = p0;
        *(__half2*)(dst + e + 2) = p1;
    }
}

// ======================= LayerNorm -> fp16 =================================
__global__ void __launch_bounds__(256) ln_half_kernel(const float* __restrict__ x,
                                                      const float* __restrict__ g,
                                                      const float* __restrict__ b,
                                                      __half* __restrict__ hi) {
    int row = blockIdx.x, tid = threadIdx.x;
    const float* xr = x + (size_t)row * CATOM;
    float v0 = xr[tid], v1 = xr[tid + 256];
    float s = v0 + v1, sq = v0*v0 + v1*v1;
    #pragma unroll
    for (int o = 16; o > 0; o >>= 1) {
        s  += __shfl_xor_sync(0xffffffffu, s,  o);
        sq += __shfl_xor_sync(0xffffffffu, sq, o);
    }
    __shared__ float ss[8], sqs[8];
    int w = tid >> 5;
    if ((tid & 31) == 0) { ss[w] = s; sqs[w] = sq; }
    __syncthreads();
    float tot = 0.f, totq = 0.f;
    #pragma unroll
    for (int i = 0; i < 8; i++) { tot += ss[i]; totq += sqs[i]; }
    float mu = tot * (1.0f/CATOM);
    float inv = rsqrtf(totq * (1.0f/CATOM) - mu*mu + 1e-5f);
    size_t o0 = (size_t)row * CATOM;
    float y0 = (v0 - mu) * inv * g[tid] + b[tid];
    float y1 = (v1 - mu) * inv * g[tid+256] + b[tid+256];
    hi[o0 + tid]       = __float2half_rn(y0);
    hi[o0 + tid + 256] = __float2half_rn(y1);
}

// ======================= shared GEMM constants =============================
#define KC 64
#define LDS 72

// ============== variant A: 128x128 block tile (large grids) ================
// 8 warps as 4x2; warp tile 32x64. 3-stage.
#define TILEH_E (128*LDS)
#define STG128_E (2*TILEH_E)
#define GEMM128_SMEM_B (3*STG128_E*2)   /* 110592 bytes */

__global__ void __launch_bounds__(256)
gemm_m128(const __half* __restrict__ A, const __half* __restrict__ B,
          const float* __restrict__ bias, const float* __restrict__ biasK,
          const float* __restrict__ biasV, const float* __restrict__ resid,
          float* __restrict__ Yf, __half* __restrict__ Yh,
          int M, int N, int K, int mode) {
    extern __shared__ __align__(16) __half smg[];

    int tid = threadIdx.x, wid = tid >> 5, lane = tid & 31;
    int n0 = blockIdx.x * 128, m0 = blockIdx.y * 128;
    int wr = wid >> 1, wc = wid & 1;
    int mb = wr * 32, nb = wc * 64;

    float acc[2][8][4];
    #pragma unroll
    for (int mt = 0; mt < 2; mt++)
        #pragma unroll
        for (int nt = 0; nt < 8; nt++)
            #pragma unroll
            for (int i = 0; i < 4; i++) acc[mt][nt][i] = 0.f;

    int lrow = lane & 15, lcol = (lane >> 4) * 8;
    const int nch = K / KC;

    int cr = tid >> 3, cs = (tid & 7) * 8;
    const __half *pa = A + (size_t)(m0 + cr) * K + cs;
    const __half *pb = B + (size_t)(n0 + cr) * K + cs;
    uint32_t sb = smem_u32(smg);
    uint32_t sco = (uint32_t)(cr*LDS + cs) * 2;

    #define G_ISSUE(st, kof) do { \
        uint32_t d_ = sb + (uint32_t)(st)*STG128_E*2; \
        _Pragma("unroll") \
        for (int i_ = 0; i_ < 4; i_++) { \
            cpa16(d_ + sco + i_*(32*LDS*2),              pa + (size_t)(i_*32)*K + (kof)); \
            cpa16(d_ + TILEH_E*2 + sco + i_*(32*LDS*2),  pb + (size_t)(i_*32)*K + (kof)); \
        } \
        CPA_COMMIT(); } while (0)

    G_ISSUE(0, 0);
    if (nch > 1) G_ISSUE(1, KC);

    int st = 0;
    for (int c = 0; c < nch; c++) {
        if (c + 1 < nch) { CPA_WAIT1(); } else { CPA_WAIT0(); }
        __syncthreads();
        if (c + 2 < nch) {
            int s2 = st + 2; if (s2 >= 3) s2 -= 3;
            G_ISSUE(s2, (c+2)*KC);
        }

        __half* pA = smg + st*STG128_E;
        __half* pB = pA + TILEH_E;

        #pragma unroll
        for (int ks = 0; ks < 4; ks++) {
            uint32_t ah[2][4];
            #pragma unroll
            for (int mt = 0; mt < 2; mt++) {
                int row = mb + mt*16 + lrow, col = ks*16 + lcol;
                ldm_x4(ah[mt], smem_u32(pA + row*LDS + col));
            }
            #pragma unroll
            for (int nbk = 0; nbk < 4; nbk++) {
                uint32_t bh[4];
                int row = nb + nbk*16 + lrow, col = ks*16 + lcol;
                ldm_x4(bh, smem_u32(pB + row*LDS + col));
                #pragma unroll
                for (int wch = 0; wch < 2; wch++) {
                    int nt = nbk*2 + wch;
                    #pragma unroll
                    for (int mt = 0; mt < 2; mt++)
                        mma_f16(acc[mt][nt], ah[mt], bh[wch], bh[wch+2]);
                }
            }
        }
        if (++st >= 3) st = 0;
    }
    #undef G_ISSUE

    int g = lane >> 2, tig = lane & 3;
    #pragma unroll
    for (int mt = 0; mt < 2; mt++) {
        #pragma unroll
        for (int half_ = 0; half_ < 2; half_++) {
            int m = m0 + mb + mt*16 + g + half_*8;
            size_t mrow = (size_t)m * N;
            #pragma unroll
            for (int nt = 0; nt < 8; nt++) {
                int n = n0 + nb + nt*8 + tig*2;
                float b0, b1;
                if (mode == 3) {
                    const float* bp = (n < 512) ? bias : (n < 1024) ? (biasK - 512) : (biasV - 1024);
                    b0 = bp[n]; b1 = bp[n+1];
                } else { b0 = bias[n]; b1 = bias[n+1]; }
                float v0 = acc[mt][nt][half_*2+0] + b0;
                float v1 = acc[mt][nt][half_*2+1] + b1;
                if (mode == 2) {
                    v0 = 0.5f * v0 * (1.0f + erff(v0 * 0.70710678118654752f));
                    v1 = 0.5f * v1 * (1.0f + erff(v1 * 0.70710678118654752f));
                    *(__half2*)(Yh + mrow + n) = __floats2half2_rn(v0, v1);
                } else if (mode == 3) {
                    int which = n >> 9, col = n & 511;
                    __half* dst = Yh + (size_t)which*MC + (size_t)m*CATOM + col;
                    *(__half2*)dst = __floats2half2_rn(v0, v1);
                } else {
                    if (mode == 1) {
                        float2 rv = *(const float2*)(resid + mrow + n);
                        v0 += rv.x; v1 += rv.y;
                    }
                    *(float2*)(Yf + mrow + n) = make_float2(v0, v1);
                }
            }
        }
    }
}

// ============== variant B: 64x128 block tile (small-N launches) ============
#define TILE_A_E (64*LDS)
#define TILE_B_E (128*LDS)
#define STG64_E (TILE_A_E + TILE_B_E)
#define GEMM64_SMEM_B (3*STG64_E*2)     /* 82944 bytes */

__global__ void __launch_bounds__(256, 2)
gemm_m64(const __half* __restrict__ A, const __half* __restrict__ B,
         const float* __restrict__ bias, const float* __restrict__ resid,
         float* __restrict__ Yf, __half* __restrict__ Yh,
         int M, int N, int K, int mode) {
    extern __shared__ __align__(16) __half smg[];

    int tid = threadIdx.x, wid = tid >> 5, lane = tid & 31;
    int n0 = blockIdx.x * 128, m0 = blockIdx.y * 64;
    int wr = wid >> 2, wc = wid & 3;
    int mb = wr * 32, nb = wc * 32;

    float acc[2][4][4];
    #pragma unroll
    for (int mt = 0; mt < 2; mt++)
        #pragma unroll
        for (int nt = 0; nt < 4; nt++)
            #pragma unroll
            for (int i = 0; i < 4; i++) acc[mt][nt][i] = 0.f;

    int lrow = lane & 15, lcol = (lane >> 4) * 8;
    const int nch = K / KC;

    int cr = tid >> 3, cs = (tid & 7) * 8;
    const __half *pa = A + (size_t)(m0 + cr) * K + cs;
    const __half *pb = B + (size_t)(n0 + cr) * K + cs;
    uint32_t sb = smem_u32(smg);
    uint32_t sco = (uint32_t)(cr*LDS + cs) * 2;

    #define G_ISSUE(st, kof) do { \
        uint32_t d_ = sb + (uint32_t)(st)*STG64_E*2; \
        _Pragma("unroll") \
        for (int i_ = 0; i_ < 2; i_++) \
            cpa16(d_ + sco + i_*(32*LDS*2), pa + (size_t)(i_*32)*K + (kof)); \
        _Pragma("unroll") \
        for (int i_ = 0; i_ < 4; i_++) \
            cpa16(d_ + TILE_A_E*2 + sco + i_*(32*LDS*2), pb + (size_t)(i_*32)*K + (kof)); \
        CPA_COMMIT(); } while (0)

    G_ISSUE(0, 0);
    if (nch > 1) G_ISSUE(1, KC);

    int st = 0;
    for (int c = 0; c < nch; c++) {
        if (c + 1 < nch) { CPA_WAIT1(); } else { CPA_WAIT0(); }
        __syncthreads();
        if (c + 2 < nch) {
            int s2 = st + 2; if (s2 >= 3) s2 -= 3;
            G_ISSUE(s2, (c+2)*KC);
        }

        __half* pA = smg + st*STG64_E;
        __half* pB = pA + TILE_A_E;

        #pragma unroll
        for (int ks = 0; ks < 4; ks++) {
            uint32_t ah[2][4];
            #pragma unroll
            for (int mt = 0; mt < 2; mt++) {
                int row = mb + mt*16 + lrow, col = ks*16 + lcol;
                ldm_x4(ah[mt], smem_u32(pA + row*LDS + col));
            }
            #pragma unroll
            for (int nbk = 0; nbk < 2; nbk++) {
                uint32_t bh[4];
                int row = nb + nbk*16 + lrow, col = ks*16 + lcol;
                ldm_x4(bh, smem_u32(pB + row*LDS + col));
                #pragma unroll
                for (int wch = 0; wch < 2; wch++) {
                    int nt = nbk*2 + wch;
                    #pragma unroll
                    for (int mt = 0; mt < 2; mt++)
                        mma_f16(acc[mt][nt], ah[mt], bh[wch], bh[wch+2]);
                }
            }
        }
        if (++st >= 3) st = 0;
    }
    #undef G_ISSUE

    int g = lane >> 2, tig = lane & 3;
    #pragma unroll
    for (int mt = 0; mt < 2; mt++) {
        #pragma unroll
        for (int half_ = 0; half_ < 2; half_++) {
            int m = m0 + mb + mt*16 + g + half_*8;
            size_t mrow = (size_t)m * N;
            #pragma unroll
            for (int nt = 0; nt < 4; nt++) {
                int n = n0 + nb + nt*8 + tig*2;
                float v0 = acc[mt][nt][half_*2+0] + bias[n];
                float v1 = acc[mt][nt][half_*2+1] + bias[n+1];
                if (mode == 2) {
                    v0 = 0.5f * v0 * (1.0f + erff(v0 * 0.70710678118654752f));
                    v1 = 0.5f * v1 * (1.0f + erff(v1 * 0.70710678118654752f));
                    *(__half2*)(Yh + mrow + n) = __floats2half2_rn(v0, v1);
                } else {
                    if (mode == 1) {
                        float2 rv = *(const float2*)(resid + mrow + n);
                        v0 += rv.x; v1 += rv.y;
                    }
                    *(float2*)(Yf + mrow + n) = make_float2(v0, v1);
                }
            }
        }
    }
}

// ================= Flash attention: fixed-shift softmax, paired chunks =====
#define AP 72
#define AQ_E (128*AP)
#define AKV_E (64*AP)
#define APAIR_E (4*AKV_E)                       /* K0,V0,K1,V1 */
#define ATTN_SMEM_B ((AQ_E + 2*APAIR_E)*2)      /* 92160 bytes */
#define SHIFT_C 3.0f

__device__ __forceinline__ void attn_issue2(__half* dst,
        const __half* kb, const __half* vb, size_t base, int j0, int tid) {
    #pragma unroll
    for (int i = 0; i < 2; i++) {
        int u = tid + i * 256;
        int r = u >> 3, seg = (u & 7) * 8;
        size_t gk0 = base + (size_t)(j0 + r) * CATOM + seg;
        size_t gk1 = base + (size_t)(j0 + 64 + r) * CATOM + seg;
        cpa16(smem_u32(dst +             r*AP + seg), kb + gk0);
        cpa16(smem_u32(dst +   AKV_E  + r*AP + seg), vb + gk0);
        cpa16(smem_u32(dst + 2*AKV_E + r*AP + seg), kb + gk1);
        cpa16(smem_u32(dst + 3*AKV_E + r*AP + seg), vb + gk1);
    }
    CPA_COMMIT();
}

__device__ __forceinline__ void attn_chunk(
        const __half* sK, const __half* sV, int j0,
        const uint32_t aQ[4][4], const float b2c[2],
        float acc[8][4], float li[2],
        const int* mrow, int msel,
        int lrow, int lcol, int vkey, int vcol, float scale) {
    float cc_[8][4];
    #pragma unroll
    for (int nt = 0; nt < 8; nt++)
        #pragma unroll
        for (int i = 0; i < 4; i++) cc_[nt][i] = 0.f;
    #pragma unroll
    for (int nbk = 0; nbk < 4; nbk++) {
        uint32_t bk[4][4];
        #pragma unroll
        for (int ks = 0; ks < 4; ks++)
            ldm_x4(bk[ks], smem_u32(sK + (nbk*16 + lrow)*AP + ks*16 + lcol));
        #pragma unroll
        for (int wch = 0; wch < 2; wch++) {
            float* cc = cc_[nbk*2 + wch];
            #pragma unroll
            for (int ks = 0; ks < 4; ks++)
                mma_f16(cc, aQ[ks], bk[ks][wch], bk[ks][wch+2]);
        }
    }

    #pragma unroll
    for (int nt = 0; nt < 8; nt++) {
        float mk = mrow[(j0 >> 2) + 2*nt + msel] ? 0.f : -1e30f;
        cc_[nt][0] = __expf(fmaf(cc_[nt][0], scale, b2c[0]) + mk);
        cc_[nt][1] = __expf(fmaf(cc_[nt][1], scale, b2c[1]) + mk);
        cc_[nt][2] = __expf(fmaf(cc_[nt][2], scale, b2c[0]) + mk);
        cc_[nt][3] = __expf(fmaf(cc_[nt][3], scale, b2c[1]) + mk);
        li[0] += cc_[nt][0] + cc_[nt][1];
        li[1] += cc_[nt][2] + cc_[nt][3];
    }

    uint32_t aP[4][4];
    #pragma unroll
    for (int ks = 0; ks < 4; ks++) {
        aP[ks][0] = pack_f16(cc_[2*ks][0],   cc_[2*ks][1]);
        aP[ks][1] = pack_f16(cc_[2*ks][2],   cc_[2*ks][3]);
        aP[ks][2] = pack_f16(cc_[2*ks+1][0], cc_[2*ks+1][1]);
        aP[ks][3] = pack_f16(cc_[2*ks+1][2], cc_[2*ks+1][3]);
    }

    #pragma unroll
    for (int nbk = 0; nbk < 4; nbk++) {
        uint32_t bv[4][4];
        #pragma unroll
        for (int ks = 0; ks < 4; ks++)
            ldm_x4_t(bv[ks], smem_u32(sV + (ks*16 + vkey)*AP + nbk*16 + vcol));
        #pragma unroll
        for (int wch = 0; wch < 2; wch++) {
            float* oo = acc[nbk*2 + wch];
            #pragma unroll
            for (int ks = 0; ks < 4; ks++)
                mma_f16(oo, aP[ks], bv[ks][wch], bv[ks][wch+2]);
        }
    }
}

__global__ void __launch_bounds__(256, 2)
attn_mma(const __half* __restrict__ qkv3, const float* __restrict__ pair_bias,
         const int* __restrict__ mask, __half* __restrict__ outb) {
    extern __shared__ __align__(16) __half sma[];
    __half* sQ = sma;
    const __half* qb = qkv3;
    const __half* kb = qkv3 + MC;
    const __half* vb = qkv3 + 2*MC;

    int q0 = blockIdx.x * 128;
    int bh = blockIdx.y;
    int b = bh >> 3, h = bh & 7;
    int tid = threadIdx.x, wid = tid >> 5, lane = tid & 31;
    int g = lane >> 2, tig = lane & 3;
    int lrow = lane & 15, lcol = (lane >> 4) * 8;
    const float scale = 0.125f;
    size_t base = (size_t)b * SEQ * CATOM + (size_t)h * HDIM;

    #pragma unroll
    for (int i = 0; i < 4; i++) {
        int u = tid + i * 256;
        int r = u >> 3, seg = (u & 7) * 8;
        cpa16(smem_u32(sQ + r*AP + seg), qb + base + (size_t)(q0 + r) * CATOM + seg);
    }
    CPA_COMMIT();
    attn_issue2(sQ + AQ_E, kb, vb, base, 0, tid);
    CPA_WAIT1();
    __syncthreads();

    uint32_t aQ[4][4];
    #pragma unroll
    for (int ks = 0; ks < 4; ks++)
        ldm_x4(aQ[ks], smem_u32(sQ + (wid*16 + lrow)*AP + ks*16 + lcol));

    float b2c[2];
    b2c[0] = pair_bias[h*16 + (g&3)*4 + ((2*tig)&3)]   - SHIFT_C;
    b2c[1] = pair_bias[h*16 + (g&3)*4 + ((2*tig+1)&3)] - SHIFT_C;

    float li[2] = {0.f, 0.f};
    float acc[8][4];
    #pragma unroll
    for (int nt = 0; nt < 8; nt++)
        #pragma unroll
        for (int i = 0; i < 4; i++) acc[nt][i] = 0.f;

    const int* mrow = mask + (size_t)b * LSEQ;
    int msel = tig >> 1;
    int vkey = (lane & 7) | ((lane & 16) >> 1);
    int vcol = lane & 8;

    const int NS = SEQ / 128;   // 16 pair-steps
    for (int s = 0; s < NS; s++) {
        int buf = s & 1;
        if (s + 1 < NS) {
            attn_issue2(sQ + AQ_E + (buf^1)*APAIR_E, kb, vb, base, (s+1)*128, tid);
            CPA_WAIT1();
        } else {
            CPA_WAIT0();
        }
        __syncthreads();
        __half* pp = sQ + AQ_E + buf*APAIR_E;
        int j0 = s * 128;

        attn_chunk(pp,             pp + AKV_E,   j0,      aQ, b2c, acc, li, mrow, msel, lrow, lcol, vkey, vcol, scale);
        attn_chunk(pp + 2*AKV_E,   pp + 3*AKV_E, j0 + 64, aQ, b2c, acc, li, mrow, msel, lrow, lcol, vkey, vcol, scale);
        __syncthreads();
    }

    #pragma unroll
    for (int o = 1; o <= 2; o <<= 1) {
        li[0] += __shfl_xor_sync(0xffffffffu, li[0], o);
        li[1] += __shfl_xor_sync(0xffffffffu, li[1], o);
    }

    float inv0 = 1.0f / li[0], inv1 = 1.0f / li[1];
    #pragma unroll
    for (int nt = 0; nt < 8; nt++) {
        size_t r0 = base + (size_t)(q0 + wid*16 + g) * CATOM + nt*8 + tig*2;
        size_t r1 = r0 + (size_t)8 * CATOM;
        *(__half2*)(outb + r0) = __floats2half2_rn(acc[nt][0]*inv0, acc[nt][1]*inv0);
        *(__half2*)(outb + r1) = __floats2half2_rn(acc[nt][2]*inv1, acc[nt][3]*inv1);
    }
}

// ---------------- driver ----------------
extern "C" void kernel_launch(void* const* d_in, const int* in_sizes, int n_in,
                              void* d_out, int out_size) {
    const float* atom = (const float*)d_in[0];
    const int* mask = (const int*)d_in[1];
    const float* ln1g = (const float*)d_in[2];
    const float* ln1b = (const float*)d_in[3];
    const float* Wq = (const float*)d_in[4];
    const float* bq = (const float*)d_in[5];
    const float* Wk = (const float*)d_in[6];
    const float* bk = (const float*)d_in[7];
    const float* Wv = (const float*)d_in[8];
    const float* bv = (const float*)d_in[9];
    const float* Wo = (const float*)d_in[10];
    const float* bo = (const float*)d_in[11];
    const float* pb = (const float*)d_in[12];
    const float* ln2g = (const float*)d_in[13];
    const float* ln2b = (const float*)d_in[14];
    const float* W1 = (const float*)d_in[15];
    const float* b1 = (const float*)d_in[16];
    const float* W2 = (const float*)d_in[17];
    const float* b2 = (const float*)d_in[18];
    float* out = (float*)d_out;

    __half *hh_, *qkv3_, *aoh_, *h2h_, *f1h_, *wf_;
    float *x1_;
    cudaGetSymbolAddress((void**)&hh_,   g_hh);
    cudaGetSymbolAddress((void**)&qkv3_, g_qkv3);
    cudaGetSymbolAddress((void**)&aoh_,  g_aoh);
    cudaGetSymbolAddress((void**)&x1_,   g_x1);
    cudaGetSymbolAddress((void**)&h2h_,  g_h2h);
    cudaGetSymbolAddress((void**)&f1h_,  g_f1h);
    cudaGetSymbolAddress((void**)&wf_,   g_wf);

    cudaFuncSetAttribute(gemm_m128, cudaFuncAttributeMaxDynamicSharedMemorySize, GEMM128_SMEM_B);
    cudaFuncSetAttribute(gemm_m64,  cudaFuncAttributeMaxDynamicSharedMemorySize, GEMM64_SMEM_B);
    cudaFuncSetAttribute(attn_mma,  cudaFuncAttributeMaxDynamicSharedMemorySize, ATTN_SMEM_B);

    // fused weight convert -> fp16 (MLP=4)
    conv6_kernel<<<WTOT/4/1024, 256>>>(Wq, Wk, Wv, Wo, W1, W2, wf_);

    // 1) h = LN1(x) -> fp16
    ln_half_kernel<<<MROWS, 256>>>(atom, ln1g, ln1b, hh_);
    // 2) fused qkv GEMM (M128 tile, grid 384); biases gathered in epilogue
    gemm_m128<<<dim3(QKVN/128, MROWS/128), 256, GEMM128_SMEM_B>>>(hh_, wf_+WOFF_Q, bq, bk, bv, nullptr, nullptr, qkv3_, MROWS, QKVN, CATOM, 3);
    // 3) attention
    attn_mma<<<dim3(SEQ/128, BATCH*NHEADS), 256, ATTN_SMEM_B>>>(qkv3_, pb, mask, aoh_);
    // 4) x1 = x + ao @ Wo^T + bo  (M64 tile, grid 256)
    gemm_m64<<<dim3(CATOM/128, MROWS/64), 256, GEMM64_SMEM_B>>>(aoh_, wf_+WOFF_O, bo, atom, x1_, nullptr, MROWS, CATOM, CATOM, 1);
    // 5) h2 = LN2(x1) -> fp16
    ln_half_kernel<<<MROWS, 256>>>(x1_, ln2g, ln2b, h2h_);
    // 6) f1 = gelu(h2 @ W1^T + b1)  (M128 tile, grid 512)
    gemm_m128<<<dim3(FFDIM/128, MROWS/128), 256, GEMM128_SMEM_B>>>(h2h_, wf_+WOFF_1, b1, nullptr, nullptr, nullptr, nullptr, f1h_, MROWS, FFDIM, CATOM, 2);
    // 7) out = x1 + f1 @ W2^T + b2  (M64 tile, grid 256, fp32 to d_out)
    gemm_m64<<<dim3(CATOM/128, MROWS/64), 256, GEMM64_SMEM_B>>>(f1h_, wf_+WOFF_2, b2, x1_, out, nullptr, MROWS, CATOM, FFDIM, 1);
}